// round 11
// baseline (speedup 1.0000x reference)
#include <cuda_runtime.h>
#include <cuda_fp16.h>
#include <mma.h>
#include <math.h>
#include <cstdint>

using namespace nvcuda;

// Problem shapes
#define BATCH 65536
#define DIN   64
#define HID   512

// Shared tile params
#define BM 128
#define BKC 64
#define LDA_H 72     // 64 + 8 pad halfs
#define NTHREADS 256
#define STAGES 3

// big kernel: BN2=256, warp tile 64x64
#define BN2 256
#define LDB2 272     // 256 + 16 pad halfs
#define A_ST_H (BM * LDA_H)                   // 9216
#define B2_ST_H 18432                          // max(256*72, 64*272)
#define ST2_H (A_ST_H + B2_ST_H)               // 27648
#define SMEM2 (STAGES * ST2_H * 2)             // 165888

// small kernel (final GEMM): BN=128, warp tile 64x32
#define BN1 128
#define LDB1 144
#define B1_ST_H 9216                           // max(128*72, 64*144)
#define ST1_H (A_ST_H + B1_ST_H)               // 18432
#define SMEM1 (STAGES * ST1_H * 2)             // 110592

// ---------------- scratch ----------------
__device__ __align__(256) __half g_xm1[BATCH * DIN];
__device__ __align__(256) __half g_s1[BATCH * HID];
__device__ __align__(256) __half g_s2[BATCH * HID];
__device__ __align__(256) __half g_s3[BATCH * HID];
__device__ __align__(256) __half g_a1[BATCH * HID];
__device__ __align__(256) __half g_a2[BATCH * HID];
__device__ __align__(256) __half g_a3[BATCH * HID];
__device__ __align__(256) __half g_d1[BATCH * HID];
__device__ __align__(256) __half g_d2[BATCH * HID];
__device__ __align__(256) __half g_d3[BATCH * HID];
__device__ __align__(256) __half g_d4[BATCH * HID];
__device__ __align__(256) __half g_wz0[HID * DIN];
__device__ __align__(256) __half g_wz1[HID * HID];
__device__ __align__(256) __half g_wz2[HID * HID];
__device__ __align__(256) __half g_wz3[HID * HID];
__device__ __align__(256) __half g_wx0[HID * DIN];
__device__ __align__(256) __half g_wx1[HID * DIN];
__device__ __align__(256) __half g_wx2[HID * DIN];

// ---------------- prep kernels ----------------
__global__ void sub1_half_kernel(const float* __restrict__ in, __half* __restrict__ out, int n) {
    int i = blockIdx.x * blockDim.x + threadIdx.x;
    if (i < n) out[i] = __float2half_rn(in[i] - 1.0f);
}

// one kernel converts ALL weights fp32 -> fp16
__global__ void prep_weights(
    const float* __restrict__ Wz0, const float* __restrict__ Wx0,
    const float* __restrict__ Wx1, const float* __restrict__ Wx2,
    const float* __restrict__ Wz1, const float* __restrict__ Wz2, const float* __restrict__ Wz3,
    __half* __restrict__ wz0, __half* __restrict__ wx0,
    __half* __restrict__ wx1, __half* __restrict__ wx2,
    __half* __restrict__ wz1, __half* __restrict__ wz2, __half* __restrict__ wz3)
{
    const int S = HID * DIN;      // 32768
    const int L = HID * HID;      // 262144
    int i = blockIdx.x * blockDim.x + threadIdx.x;
    if (i < 4 * S) {
        int seg = i / S, off = i - seg * S;
        const float* src = (seg == 0) ? Wz0 : (seg == 1) ? Wx0 : (seg == 2) ? Wx1 : Wx2;
        __half* dst      = (seg == 0) ? wz0 : (seg == 1) ? wx0 : (seg == 2) ? wx1 : wx2;
        dst[off] = __float2half_rn(src[off]);
    } else {
        int j = i - 4 * S;
        if (j < 3 * L) {
            int seg = j / L, off = j - seg * L;
            const float* src = (seg == 0) ? Wz1 : (seg == 1) ? Wz2 : Wz3;
            __half* dst      = (seg == 0) ? wz1 : (seg == 1) ? wz2 : wz3;
            dst[off] = __float2half_rn(src[off]);
        }
    }
}

// ---------------- helpers ----------------
__device__ __forceinline__ float softplusf(float p) { return (p > 20.0f) ? p : log1pf(expf(p)); }
__device__ __forceinline__ float sigmoidf_(float p) { return 1.0f / (1.0f + expf(-p)); }

__device__ __forceinline__ void cp_async16(__half* smem_dst, const __half* gmem_src, bool pred) {
    unsigned int s = (unsigned int)__cvta_generic_to_shared(smem_dst);
    int bytes = pred ? 16 : 0;
    asm volatile("cp.async.cg.shared.global [%0], [%1], 16, %2;\n"
                 :: "r"(s), "l"(gmem_src), "r"(bytes));
}
__device__ __forceinline__ void cp_commit() { asm volatile("cp.async.commit_group;\n" ::: "memory"); }
__device__ __forceinline__ void cp_wait0() { asm volatile("cp.async.wait_group 0;\n" ::: "memory"); }
__device__ __forceinline__ void cp_wait1() { asm volatile("cp.async.wait_group 1;\n" ::: "memory"); }

#define MODE_FWD 0
#define MODE_L4  1
#define MODE_BWD 2
#define MODE_FIN 3

__device__ __forceinline__ void get_iter(
    int it,
    const __half* A0, const __half* W0, int K0,
    const __half* A1, const __half* W1, int K1,
    const __half* A2, const __half* W2, int K2,
    const __half* A3, const __half* W3, int K3,
    const __half*& A, const __half*& W, int& K, int& k0)
{
    int n0 = K0 >> 6;
    if (it < n0) { A = A0; W = W0; K = K0; k0 = it << 6; return; }
    it -= n0;
    int n1 = K1 >> 6;
    if (it < n1) { A = A1; W = W1; K = K1; k0 = it << 6; return; }
    it -= n1;
    int n2 = K2 >> 6;
    if (it < n2) { A = A2; W = W2; K = K2; k0 = it << 6; return; }
    it -= n2;
    A = A3; W = W3; K = K3; k0 = it << 6;
}

// ================= BIG kernel: BM=128, BN=256, warp tile 64x64 =================
template<bool BT>
__device__ __forceinline__ void stage2(
    __half* sA, __half* sW,
    const __half* __restrict__ A, const __half* __restrict__ W,
    int K, int k0, int m0, int n0, int tid)
{
    #pragma unroll
    for (int t = 0; t < 4; t++) {
        int slot = tid + t * NTHREADS;
        int row = slot >> 3, kq = slot & 7;
        cp_async16(&sA[row * LDA_H + (kq << 3)],
                   A + (size_t)(m0 + row) * K + k0 + (kq << 3), true);
    }
    if (BT) {
        // W [N,K]: rows n0..n0+255 -> sW[n*LDA_H + k]; 2048 chunks, 8/thread
        #pragma unroll
        for (int t = 0; t < 8; t++) {
            int slot = tid + t * NTHREADS;
            int n = slot >> 3, kq = slot & 7;
            cp_async16(&sW[n * LDA_H + (kq << 3)],
                       W + (size_t)(n0 + n) * K + k0 + (kq << 3), true);
        }
    } else {
        // W [K,N]: 64 rows x 32 n-chunks -> sW[k*LDB2 + n]; 2048 chunks
        #pragma unroll
        for (int t = 0; t < 8; t++) {
            int slot = tid + t * NTHREADS;
            int krow = slot >> 5, nq = slot & 31;
            cp_async16(&sW[krow * LDB2 + (nq << 3)],
                       W + (size_t)(k0 + krow) * HID + n0 + (nq << 3), true);
        }
    }
}

template<bool BT, int MODE>
__global__ void __launch_bounds__(NTHREADS)
gemm_big(const __half* __restrict__ A0, const __half* __restrict__ W0, int K0,
         const __half* __restrict__ A1, const __half* __restrict__ W1, int K1,
         const float* __restrict__ bias,
         const float* __restrict__ vecn,
         const __half* __restrict__ sgate,
         __half* __restrict__ out1h,
         __half* __restrict__ out2h)
{
    extern __shared__ __half smem_h[];

    const int tid    = threadIdx.x;
    const int warpId = tid >> 5;
    const int lane   = tid & 31;
    const int wm     = warpId >> 2;   // 0..1 (64-row slab)
    const int wn     = warpId & 3;    // 0..3 (64-col slab)
    const int m0     = blockIdx.y * BM;
    const int n0     = blockIdx.x * BN2;

    wmma::fragment<wmma::accumulator, 16, 16, 16, float> acc[4][4];
    #pragma unroll
    for (int i = 0; i < 4; i++)
        #pragma unroll
        for (int j = 0; j < 4; j++)
            wmma::fill_fragment(acc[i][j], 0.0f);

    const int niter = (K0 >> 6) + (K1 >> 6);

    #pragma unroll
    for (int j = 0; j < 2; j++) {
        if (j < niter) {
            const __half *A, *W; int K, k0;
            get_iter(j, A0,W0,K0, A1,W1,K1, nullptr,nullptr,0, nullptr,nullptr,0, A, W, K, k0);
            stage2<BT>(smem_h + j * ST2_H, smem_h + j * ST2_H + A_ST_H, A, W, K, k0, m0, n0, tid);
            cp_commit();
        }
    }

    for (int it = 0; it < niter; ++it) {
        if (it + 1 < niter) cp_wait1(); else cp_wait0();
        __syncthreads();

        const int nxt = it + 2;
        if (nxt < niter) {
            const __half *A, *W; int K, k0;
            get_iter(nxt, A0,W0,K0, A1,W1,K1, nullptr,nullptr,0, nullptr,nullptr,0, A, W, K, k0);
            __half* nb = smem_h + (nxt % STAGES) * ST2_H;
            stage2<BT>(nb, nb + A_ST_H, A, W, K, k0, m0, n0, tid);
            cp_commit();
        }

        __half* sA = smem_h + (it % STAGES) * ST2_H;
        __half* sW = sA + A_ST_H;

        #pragma unroll
        for (int kk = 0; kk < BKC; kk += 16) {
            wmma::fragment<wmma::matrix_a, 16, 16, 16, __half, wmma::row_major> af[4];
            #pragma unroll
            for (int i = 0; i < 4; i++)
                wmma::load_matrix_sync(af[i], &sA[(wm * 64 + i * 16) * LDA_H + kk], LDA_H);
            if (BT) {
                wmma::fragment<wmma::matrix_b, 16, 16, 16, __half, wmma::col_major> bf[4];
                #pragma unroll
                for (int j = 0; j < 4; j++)
                    wmma::load_matrix_sync(bf[j], &sW[(wn * 64 + j * 16) * LDA_H + kk], LDA_H);
                #pragma unroll
                for (int i = 0; i < 4; i++)
                    #pragma unroll
                    for (int j = 0; j < 4; j++)
                        wmma::mma_sync(acc[i][j], af[i], bf[j], acc[i][j]);
            } else {
                wmma::fragment<wmma::matrix_b, 16, 16, 16, __half, wmma::row_major> bf[4];
                #pragma unroll
                for (int j = 0; j < 4; j++)
                    wmma::load_matrix_sync(bf[j], &sW[kk * LDB2 + wn * 64 + j * 16], LDB2);
                #pragma unroll
                for (int i = 0; i < 4; i++)
                    #pragma unroll
                    for (int j = 0; j < 4; j++)
                        wmma::mma_sync(acc[i][j], af[i], bf[j], acc[i][j]);
            }
        }
    }

    // epilogue
    __syncthreads();
    float* ep = reinterpret_cast<float*>(smem_h) + warpId * 288;

    #pragma unroll
    for (int i = 0; i < 4; i++) {
        #pragma unroll
        for (int j = 0; j < 4; j++) {
            const int rbase = m0 + wm * 64 + i * 16;
            const int cbase = n0 + wn * 64 + j * 16;
            wmma::store_matrix_sync(ep, acc[i][j], 16, wmma::mem_row_major);
            __syncwarp();
            #pragma unroll
            for (int e = 0; e < 8; e++) {
                int lin = e * 32 + lane;
                int r = lin >> 4;
                int c = lin & 15;
                int col = cbase + c;
                float p = ep[lin];
                size_t oi = (size_t)(rbase + r) * HID + col;
                if (MODE == MODE_FWD) {
                    p += bias[col];
                    out1h[oi] = __float2half_rn(sigmoidf_(p));
                    out2h[oi] = __float2half_rn(softplusf(p));
                } else if (MODE == MODE_L4) {
                    p += bias[col];
                    out1h[oi] = __float2half_rn(vecn[col] * sigmoidf_(p));
                } else { // MODE_BWD
                    out1h[oi] = __float2half_rn(__half2float(sgate[oi]) * p);
                }
            }
            __syncwarp();
        }
    }
}

// ================= small kernel for final GEMM (N=64), BT=false =================
__device__ __forceinline__ void stage1(
    __half* sA, __half* sW,
    const __half* __restrict__ A, const __half* __restrict__ W,
    int K, int k0, int m0, int N, int tid)
{
    #pragma unroll
    for (int t = 0; t < 4; t++) {
        int slot = tid + t * NTHREADS;
        int row = slot >> 3, kq = slot & 7;
        cp_async16(&sA[row * LDA_H + (kq << 3)],
                   A + (size_t)(m0 + row) * K + k0 + (kq << 3), true);
    }
    #pragma unroll
    for (int t = 0; t < 4; t++) {
        int slot = tid + t * NTHREADS;
        int krow = slot >> 4, nq = slot & 15;
        int col = nq << 3;
        cp_async16(&sW[krow * LDB1 + col],
                   W + (size_t)(k0 + krow) * N + col, col < N);
    }
}

__global__ void __launch_bounds__(NTHREADS, 2)
gemm_fin(const __half* __restrict__ A0, const __half* __restrict__ W0, int K0,
         const __half* __restrict__ A1, const __half* __restrict__ W1, int K1,
         const __half* __restrict__ A2, const __half* __restrict__ W2, int K2,
         const __half* __restrict__ A3, const __half* __restrict__ W3, int K3,
         int N,
         const float* __restrict__ vecn,
         float* __restrict__ out1f)
{
    extern __shared__ __half smem_h[];

    const int tid    = threadIdx.x;
    const int warpId = tid >> 5;
    const int lane   = tid & 31;
    const int wm     = warpId >> 2;
    const int wn     = warpId & 3;
    const int m0     = blockIdx.y * BM;

    wmma::fragment<wmma::accumulator, 16, 16, 16, float> acc[4][2];
    #pragma unroll
    for (int i = 0; i < 4; i++)
        #pragma unroll
        for (int j = 0; j < 2; j++)
            wmma::fill_fragment(acc[i][j], 0.0f);

    const int niter = (K0 >> 6) + (K1 >> 6) + (K2 >> 6) + (K3 >> 6);

    #pragma unroll
    for (int j = 0; j < 2; j++) {
        if (j < niter) {
            const __half *A, *W; int K, k0;
            get_iter(j, A0,W0,K0, A1,W1,K1, A2,W2,K2, A3,W3,K3, A, W, K, k0);
            stage1(smem_h + j * ST1_H, smem_h + j * ST1_H + A_ST_H, A, W, K, k0, m0, N, tid);
            cp_commit();
        }
    }

    for (int it = 0; it < niter; ++it) {
        if (it + 1 < niter) cp_wait1(); else cp_wait0();
        __syncthreads();

        const int nxt = it + 2;
        if (nxt < niter) {
            const __half *A, *W; int K, k0;
            get_iter(nxt, A0,W0,K0, A1,W1,K1, A2,W2,K2, A3,W3,K3, A, W, K, k0);
            __half* nb = smem_h + (nxt % STAGES) * ST1_H;
            stage1(nb, nb + A_ST_H, A, W, K, k0, m0, N, tid);
            cp_commit();
        }

        __half* sA = smem_h + (it % STAGES) * ST1_H;
        __half* sW = sA + A_ST_H;

        #pragma unroll
        for (int kk = 0; kk < BKC; kk += 16) {
            wmma::fragment<wmma::matrix_a, 16, 16, 16, __half, wmma::row_major> af[4];
            #pragma unroll
            for (int i = 0; i < 4; i++)
                wmma::load_matrix_sync(af[i], &sA[(wm * 64 + i * 16) * LDA_H + kk], LDA_H);
            wmma::fragment<wmma::matrix_b, 16, 16, 16, __half, wmma::row_major> bf[2];
            #pragma unroll
            for (int j = 0; j < 2; j++)
                wmma::load_matrix_sync(bf[j], &sW[kk * LDB1 + wn * 32 + j * 16], LDB1);
            #pragma unroll
            for (int i = 0; i < 4; i++)
                #pragma unroll
                for (int j = 0; j < 2; j++)
                    wmma::mma_sync(acc[i][j], af[i], bf[j], acc[i][j]);
        }
    }

    __syncthreads();
    float* ep = reinterpret_cast<float*>(smem_h) + warpId * 288;

    #pragma unroll
    for (int i = 0; i < 4; i++) {
        #pragma unroll
        for (int j = 0; j < 2; j++) {
            const int rbase = m0 + wm * 64 + i * 16;
            const int cbase = wn * 32 + j * 16;
            wmma::store_matrix_sync(ep, acc[i][j], 16, wmma::mem_row_major);
            __syncwarp();
            #pragma unroll
            for (int e = 0; e < 8; e++) {
                int lin = e * 32 + lane;
                int r = lin >> 4;
                int c = lin & 15;
                int col = cbase + c;
                if (col < N) {
                    float p = ep[lin];
                    size_t oi = (size_t)(rbase + r) * N + col;
                    out1f[oi] = p + vecn[col];
                }
            }
            __syncwarp();
        }
    }
}

// ---------------- host launcher ----------------
extern "C" void kernel_launch(void* const* d_in, const int* in_sizes, int n_in,
                              void* d_out, int out_size)
{
    const float* state = (const float*)d_in[0];
    const float* Wz0   = (const float*)d_in[1];
    const float* bz0   = (const float*)d_in[2];
    const float* Wz1   = (const float*)d_in[3];
    const float* Wz2   = (const float*)d_in[4];
    const float* Wz3   = (const float*)d_in[5];
    const float* WzL   = (const float*)d_in[6];
    const float* Wx0   = (const float*)d_in[7];
    const float* bx0   = (const float*)d_in[8];
    const float* Wx1   = (const float*)d_in[9];
    const float* bx1   = (const float*)d_in[10];
    const float* Wx2   = (const float*)d_in[11];
    const float* bx2   = (const float*)d_in[12];
    const float* WxL   = (const float*)d_in[13];
    float* out = (float*)d_out;

    cudaFuncSetAttribute(gemm_big<true,  MODE_FWD>, cudaFuncAttributeMaxDynamicSharedMemorySize, SMEM2);
    cudaFuncSetAttribute(gemm_big<true,  MODE_L4>,  cudaFuncAttributeMaxDynamicSharedMemorySize, SMEM2);
    cudaFuncSetAttribute(gemm_big<false, MODE_BWD>, cudaFuncAttributeMaxDynamicSharedMemorySize, SMEM2);
    cudaFuncSetAttribute(gemm_fin, cudaFuncAttributeMaxDynamicSharedMemorySize, SMEM1);

    void* p;
    __half *xm1, *s1, *s2, *s3, *a1, *a2, *a3, *d1, *d2, *d3, *d4;
    __half *wz0, *wz1, *wz2, *wz3, *wx0, *wx1, *wx2;
    cudaGetSymbolAddress(&p, g_xm1);  xm1  = (__half*)p;
    cudaGetSymbolAddress(&p, g_s1);   s1   = (__half*)p;
    cudaGetSymbolAddress(&p, g_s2);   s2   = (__half*)p;
    cudaGetSymbolAddress(&p, g_s3);   s3   = (__half*)p;
    cudaGetSymbolAddress(&p, g_a1);   a1   = (__half*)p;
    cudaGetSymbolAddress(&p, g_a2);   a2   = (__half*)p;
    cudaGetSymbolAddress(&p, g_a3);   a3   = (__half*)p;
    cudaGetSymbolAddress(&p, g_d1);   d1   = (__half*)p;
    cudaGetSymbolAddress(&p, g_d2);   d2   = (__half*)p;
    cudaGetSymbolAddress(&p, g_d3);   d3   = (__half*)p;
    cudaGetSymbolAddress(&p, g_d4);   d4   = (__half*)p;
    cudaGetSymbolAddress(&p, g_wz0);  wz0  = (__half*)p;
    cudaGetSymbolAddress(&p, g_wz1);  wz1  = (__half*)p;
    cudaGetSymbolAddress(&p, g_wz2);  wz2  = (__half*)p;
    cudaGetSymbolAddress(&p, g_wz3);  wz3  = (__half*)p;
    cudaGetSymbolAddress(&p, g_wx0);  wx0  = (__half*)p;
    cudaGetSymbolAddress(&p, g_wx1);  wx1  = (__half*)p;
    cudaGetSymbolAddress(&p, g_wx2);  wx2  = (__half*)p;

    const int nX = BATCH * DIN;
    sub1_half_kernel<<<(nX + 255) / 256, 256>>>(state, xm1, nX);

    const int nW = 4 * HID * DIN + 3 * HID * HID;   // 917504
    prep_weights<<<(nW + 255) / 256, 256>>>(Wz0, Wx0, Wx1, Wx2, Wz1, Wz2, Wz3,
                                            wz0, wx0, wx1, wx2, wz1, wz2, wz3);

    dim3 blk(NTHREADS);
    dim3 gB(HID / BN2, BATCH / BM);   // (2, 512)
    dim3 gF(1, BATCH / BM);           // (1, 512)

    // Forward (BT=true: B = W^T, W [N,K] row-major)
    gemm_big<true, MODE_FWD><<<gB, blk, SMEM2>>>(xm1, wz0, DIN,
        nullptr, nullptr, 0, bz0, nullptr, nullptr, s1, a1);
    gemm_big<true, MODE_FWD><<<gB, blk, SMEM2>>>(a1, wz1, HID,
        xm1, wx0, DIN, bx0, nullptr, nullptr, s2, a2);
    gemm_big<true, MODE_FWD><<<gB, blk, SMEM2>>>(a2, wz2, HID,
        xm1, wx1, DIN, bx1, nullptr, nullptr, s3, a3);
    gemm_big<true, MODE_L4><<<gB, blk, SMEM2>>>(a3, wz3, HID,
        xm1, wx2, DIN, bx2, WzL, nullptr, d4, nullptr);

    // Backward: d_k = s_k * (d_{k+1} @ Wz_{k+1}); Wz [K,N] row-major -> BT=false
    gemm_big<false, MODE_BWD><<<gB, blk, SMEM2>>>(d4, wz3, HID,
        nullptr, nullptr, 0, nullptr, nullptr, s3, d3, nullptr);
    gemm_big<false, MODE_BWD><<<gB, blk, SMEM2>>>(d3, wz2, HID,
        nullptr, nullptr, 0, nullptr, nullptr, s2, d2, nullptr);
    gemm_big<false, MODE_BWD><<<gB, blk, SMEM2>>>(d2, wz1, HID,
        nullptr, nullptr, 0, nullptr, nullptr, s1, d1, nullptr);

    // Final: action = WxL + d1@Wz0 + d2@Wx0 + d3@Wx1 + d4@Wx2  (all [HID,DIN] = [K,N])
    gemm_fin<<<gF, blk, SMEM1>>>(d1, wz0, HID,
        d2, wx0, HID, d3, wx1, HID, d4, wx2, HID,
        DIN, WxL, out);
}

// round 12
// speedup vs baseline: 1.3589x; 1.3589x over previous
#include <cuda_runtime.h>
#include <cuda_fp16.h>
#include <mma.h>
#include <math.h>
#include <cstdint>

using namespace nvcuda;

// Problem shapes
#define BATCH 65536
#define DIN   64
#define HID   512

// GEMM tile config (fp16 operands, fp32 accum) — R10 proven config
#define BM 128
#define BN 128
#define BKC 64
#define LDA_H 72     // 64 + 8 pad halfs
#define LDB_H 144    // 128 + 16 pad halfs
#define NTHREADS 256
#define STAGES 3

#define A_STAGE_HALFS (BM * LDA_H)     // 9216
#define W_STAGE_HALFS 9216             // max(128*72, 64*144)
#define STAGE_HALFS  (A_STAGE_HALFS + W_STAGE_HALFS)   // 18432
#define SMEM_BYTES   (STAGES * STAGE_HALFS * 2)        // 110592 -> 2 CTAs/SM

// ---------------- scratch ----------------
__device__ __align__(256) __half g_xm1[BATCH * DIN];
__device__ __align__(256) __half g_s1[BATCH * HID];
__device__ __align__(256) __half g_s2[BATCH * HID];
__device__ __align__(256) __half g_s3[BATCH * HID];
__device__ __align__(256) __half g_a1[BATCH * HID];
__device__ __align__(256) __half g_a2[BATCH * HID];
__device__ __align__(256) __half g_a3[BATCH * HID];
__device__ __align__(256) __half g_d1[BATCH * HID];
__device__ __align__(256) __half g_d2[BATCH * HID];
__device__ __align__(256) __half g_d3[BATCH * HID];
__device__ __align__(256) __half g_d4[BATCH * HID];
__device__ __align__(256) __half g_wz0[HID * DIN];
__device__ __align__(256) __half g_wz1[HID * HID];
__device__ __align__(256) __half g_wz2[HID * HID];
__device__ __align__(256) __half g_wz3[HID * HID];
__device__ __align__(256) __half g_wx0[HID * DIN];
__device__ __align__(256) __half g_wx1[HID * DIN];
__device__ __align__(256) __half g_wx2[HID * DIN];

// ---------------- prep kernels ----------------
__global__ void sub1_half_kernel(const float* __restrict__ in, __half* __restrict__ out, int n) {
    int i = blockIdx.x * blockDim.x + threadIdx.x;
    if (i < n) out[i] = __float2half_rn(in[i] - 1.0f);
}

// one kernel converts ALL weights fp32 -> fp16
__global__ void prep_weights(
    const float* __restrict__ Wz0, const float* __restrict__ Wx0,
    const float* __restrict__ Wx1, const float* __restrict__ Wx2,
    const float* __restrict__ Wz1, const float* __restrict__ Wz2, const float* __restrict__ Wz3,
    __half* __restrict__ wz0, __half* __restrict__ wx0,
    __half* __restrict__ wx1, __half* __restrict__ wx2,
    __half* __restrict__ wz1, __half* __restrict__ wz2, __half* __restrict__ wz3)
{
    const int S = HID * DIN;      // 32768
    const int L = HID * HID;      // 262144
    int i = blockIdx.x * blockDim.x + threadIdx.x;
    if (i < 4 * S) {
        int seg = i / S, off = i - seg * S;
        const float* src = (seg == 0) ? Wz0 : (seg == 1) ? Wx0 : (seg == 2) ? Wx1 : Wx2;
        __half* dst      = (seg == 0) ? wz0 : (seg == 1) ? wx0 : (seg == 2) ? wx1 : wx2;
        dst[off] = __float2half_rn(src[off]);
    } else {
        int j = i - 4 * S;
        if (j < 3 * L) {
            int seg = j / L, off = j - seg * L;
            const float* src = (seg == 0) ? Wz1 : (seg == 1) ? Wz2 : Wz3;
            __half* dst      = (seg == 0) ? wz1 : (seg == 1) ? wz2 : wz3;
            dst[off] = __float2half_rn(src[off]);
        }
    }
}

// ---------------- helpers ----------------
__device__ __forceinline__ float softplusf(float p) { return (p > 20.0f) ? p : log1pf(expf(p)); }
__device__ __forceinline__ float sigmoidf_(float p) { return 1.0f / (1.0f + expf(-p)); }

__device__ __forceinline__ void cp_async16(__half* smem_dst, const __half* gmem_src, bool pred) {
    unsigned int s = (unsigned int)__cvta_generic_to_shared(smem_dst);
    int bytes = pred ? 16 : 0;
    asm volatile("cp.async.cg.shared.global [%0], [%1], 16, %2;\n"
                 :: "r"(s), "l"(gmem_src), "r"(bytes));
}
__device__ __forceinline__ void cp_commit() { asm volatile("cp.async.commit_group;\n" ::: "memory"); }
__device__ __forceinline__ void cp_wait0() { asm volatile("cp.async.wait_group 0;\n" ::: "memory"); }
__device__ __forceinline__ void cp_wait1() { asm volatile("cp.async.wait_group 1;\n" ::: "memory"); }

// Epilogue modes
#define MODE_FWD 0
#define MODE_L4  1
#define MODE_BWD 2
#define MODE_FIN 3

__device__ __forceinline__ void get_iter(
    int it,
    const __half* A0, const __half* W0, int K0,
    const __half* A1, const __half* W1, int K1,
    const __half* A2, const __half* W2, int K2,
    const __half* A3, const __half* W3, int K3,
    const __half*& A, const __half*& W, int& K, int& k0)
{
    int n0 = K0 >> 6;
    if (it < n0) { A = A0; W = W0; K = K0; k0 = it << 6; return; }
    it -= n0;
    int n1 = K1 >> 6;
    if (it < n1) { A = A1; W = W1; K = K1; k0 = it << 6; return; }
    it -= n1;
    int n2 = K2 >> 6;
    if (it < n2) { A = A2; W = W2; K = K2; k0 = it << 6; return; }
    it -= n2;
    A = A3; W = W3; K = K3; k0 = it << 6;
}

// Stage one K-chunk: A tile [128 x 64] halfs; W tile.
// BT=true : W [N,K] row-major -> sW[n*LDA_H + k]
// BT=false: W [K,N] row-major -> sW[k*LDB_H + n]
template<bool BT>
__device__ __forceinline__ void stage_tiles(
    __half* sA, __half* sW,
    const __half* __restrict__ A, const __half* __restrict__ W,
    int K, int k0, int m0, int n0, int N, int tid)
{
    #pragma unroll
    for (int t = 0; t < 4; t++) {
        int slot = tid + t * NTHREADS;
        int row = slot >> 3, kq = slot & 7;
        cp_async16(&sA[row * LDA_H + (kq << 3)],
                   A + (size_t)(m0 + row) * K + k0 + (kq << 3), true);
    }
    if (BT) {
        #pragma unroll
        for (int t = 0; t < 4; t++) {
            int slot = tid + t * NTHREADS;
            int n = slot >> 3, kq = slot & 7;
            cp_async16(&sW[n * LDA_H + (kq << 3)],
                       W + (size_t)(n0 + n) * K + k0 + (kq << 3), true);
        }
    } else {
        #pragma unroll
        for (int t = 0; t < 4; t++) {
            int slot = tid + t * NTHREADS;
            int krow = slot >> 4, nq = slot & 15;
            int col = n0 + (nq << 3);
            cp_async16(&sW[krow * LDB_H + (nq << 3)],
                       W + (size_t)(k0 + krow) * N + col, col < N);
        }
    }
}

// fp16 fused GEMM, 3-stage cp.async ring, one __syncthreads per iteration.
template<bool BT, int MODE>
__global__ void __launch_bounds__(NTHREADS, 2)
gemm_h(const __half* __restrict__ A0, const __half* __restrict__ W0, int K0,
       const __half* __restrict__ A1, const __half* __restrict__ W1, int K1,
       const __half* __restrict__ A2, const __half* __restrict__ W2, int K2,
       const __half* __restrict__ A3, const __half* __restrict__ W3, int K3,
       int N,
       const float* __restrict__ bias,
       const float* __restrict__ vecn,
       const __half* __restrict__ sgate,
       __half* __restrict__ out1h,
       __half* __restrict__ out2h,
       float* __restrict__ out1f)
{
    extern __shared__ __half smem_h[];

    const int tid    = threadIdx.x;
    const int warpId = tid >> 5;
    const int lane   = tid & 31;
    const int wm     = warpId >> 2;   // 0..1
    const int wn     = warpId & 3;    // 0..3
    const int m0     = blockIdx.y * BM;
    const int n0     = blockIdx.x * BN;

    wmma::fragment<wmma::accumulator, 16, 16, 16, float> acc[4][2];
    #pragma unroll
    for (int i = 0; i < 4; i++)
        #pragma unroll
        for (int j = 0; j < 2; j++)
            wmma::fill_fragment(acc[i][j], 0.0f);

    const int niter = (K0 >> 6) + (K1 >> 6) + (K2 >> 6) + (K3 >> 6);

    // prologue: stage chunk 0 and 1
    #pragma unroll
    for (int j = 0; j < 2; j++) {
        if (j < niter) {
            const __half *A, *W; int K, k0;
            get_iter(j, A0,W0,K0, A1,W1,K1, A2,W2,K2, A3,W3,K3, A, W, K, k0);
            stage_tiles<BT>(smem_h + j * STAGE_HALFS,
                            smem_h + j * STAGE_HALFS + A_STAGE_HALFS,
                            A, W, K, k0, m0, n0, N, tid);
            cp_commit();
        }
    }

    for (int it = 0; it < niter; ++it) {
        if (it + 1 < niter) cp_wait1(); else cp_wait0();
        __syncthreads();

        const int nxt = it + 2;
        if (nxt < niter) {
            const __half *A, *W; int K, k0;
            get_iter(nxt, A0,W0,K0, A1,W1,K1, A2,W2,K2, A3,W3,K3, A, W, K, k0);
            __half* nb = smem_h + (nxt % STAGES) * STAGE_HALFS;
            stage_tiles<BT>(nb, nb + A_STAGE_HALFS, A, W, K, k0, m0, n0, N, tid);
            cp_commit();
        }

        __half* sA = smem_h + (it % STAGES) * STAGE_HALFS;
        __half* sW = sA + A_STAGE_HALFS;

        #pragma unroll
        for (int kk = 0; kk < BKC; kk += 16) {
            wmma::fragment<wmma::matrix_a, 16, 16, 16, __half, wmma::row_major> af[4];
            #pragma unroll
            for (int i = 0; i < 4; i++)
                wmma::load_matrix_sync(af[i], &sA[(wm * 64 + i * 16) * LDA_H + kk], LDA_H);
            if (BT) {
                wmma::fragment<wmma::matrix_b, 16, 16, 16, __half, wmma::col_major> bf[2];
                #pragma unroll
                for (int j = 0; j < 2; j++)
                    wmma::load_matrix_sync(bf[j], &sW[(wn * 32 + j * 16) * LDA_H + kk], LDA_H);
                #pragma unroll
                for (int i = 0; i < 4; i++)
                    #pragma unroll
                    for (int j = 0; j < 2; j++)
                        wmma::mma_sync(acc[i][j], af[i], bf[j], acc[i][j]);
            } else {
                wmma::fragment<wmma::matrix_b, 16, 16, 16, __half, wmma::row_major> bf[2];
                #pragma unroll
                for (int j = 0; j < 2; j++)
                    wmma::load_matrix_sync(bf[j], &sW[kk * LDB_H + wn * 32 + j * 16], LDB_H);
                #pragma unroll
                for (int i = 0; i < 4; i++)
                    #pragma unroll
                    for (int j = 0; j < 2; j++)
                        wmma::mma_sync(acc[i][j], af[i], bf[j], acc[i][j]);
            }
        }
    }

    // ---- epilogue ----
    __syncthreads();
    float* ep = reinterpret_cast<float*>(smem_h) + warpId * 288;

    #pragma unroll
    for (int i = 0; i < 4; i++) {
        #pragma unroll
        for (int j = 0; j < 2; j++) {
            const int rbase = m0 + wm * 64 + i * 16;
            const int cbase = n0 + wn * 32 + j * 16;
            wmma::store_matrix_sync(ep, acc[i][j], 16, wmma::mem_row_major);
            __syncwarp();
            #pragma unroll
            for (int e = 0; e < 8; e++) {
                int lin = e * 32 + lane;
                int r = lin >> 4;
                int c = lin & 15;
                int col = cbase + c;
                if (col < N) {
                    float p = ep[lin];
                    size_t oi = (size_t)(rbase + r) * N + col;
                    if (MODE == MODE_FWD) {
                        p += bias[col];
                        out1h[oi] = __float2half_rn(sigmoidf_(p));
                        out2h[oi] = __float2half_rn(softplusf(p));
                    } else if (MODE == MODE_L4) {
                        p += bias[col];
                        out1h[oi] = __float2half_rn(vecn[col] * sigmoidf_(p));
                    } else if (MODE == MODE_BWD) {
                        out1h[oi] = __float2half_rn(__half2float(sgate[oi]) * p);
                    } else { // MODE_FIN
                        out1f[oi] = p + vecn[col];
                    }
                }
            }
            __syncwarp();
        }
    }
}

// ---------------- host launcher ----------------
extern "C" void kernel_launch(void* const* d_in, const int* in_sizes, int n_in,
                              void* d_out, int out_size)
{
    const float* state = (const float*)d_in[0];
    const float* Wz0   = (const float*)d_in[1];
    const float* bz0   = (const float*)d_in[2];
    const float* Wz1   = (const float*)d_in[3];
    const float* Wz2   = (const float*)d_in[4];
    const float* Wz3   = (const float*)d_in[5];
    const float* WzL   = (const float*)d_in[6];
    const float* Wx0   = (const float*)d_in[7];
    const float* bx0   = (const float*)d_in[8];
    const float* Wx1   = (const float*)d_in[9];
    const float* bx1   = (const float*)d_in[10];
    const float* Wx2   = (const float*)d_in[11];
    const float* bx2   = (const float*)d_in[12];
    const float* WxL   = (const float*)d_in[13];
    float* out = (float*)d_out;

    cudaFuncSetAttribute(gemm_h<true,  MODE_FWD>, cudaFuncAttributeMaxDynamicSharedMemorySize, SMEM_BYTES);
    cudaFuncSetAttribute(gemm_h<true,  MODE_L4>,  cudaFuncAttributeMaxDynamicSharedMemorySize, SMEM_BYTES);
    cudaFuncSetAttribute(gemm_h<false, MODE_BWD>, cudaFuncAttributeMaxDynamicSharedMemorySize, SMEM_BYTES);
    cudaFuncSetAttribute(gemm_h<false, MODE_FIN>, cudaFuncAttributeMaxDynamicSharedMemorySize, SMEM_BYTES);

    void* p;
    __half *xm1, *s1, *s2, *s3, *a1, *a2, *a3, *d1, *d2, *d3, *d4;
    __half *wz0, *wz1, *wz2, *wz3, *wx0, *wx1, *wx2;
    cudaGetSymbolAddress(&p, g_xm1);  xm1  = (__half*)p;
    cudaGetSymbolAddress(&p, g_s1);   s1   = (__half*)p;
    cudaGetSymbolAddress(&p, g_s2);   s2   = (__half*)p;
    cudaGetSymbolAddress(&p, g_s3);   s3   = (__half*)p;
    cudaGetSymbolAddress(&p, g_a1);   a1   = (__half*)p;
    cudaGetSymbolAddress(&p, g_a2);   a2   = (__half*)p;
    cudaGetSymbolAddress(&p, g_a3);   a3   = (__half*)p;
    cudaGetSymbolAddress(&p, g_d1);   d1   = (__half*)p;
    cudaGetSymbolAddress(&p, g_d2);   d2   = (__half*)p;
    cudaGetSymbolAddress(&p, g_d3);   d3   = (__half*)p;
    cudaGetSymbolAddress(&p, g_d4);   d4   = (__half*)p;
    cudaGetSymbolAddress(&p, g_wz0);  wz0  = (__half*)p;
    cudaGetSymbolAddress(&p, g_wz1);  wz1  = (__half*)p;
    cudaGetSymbolAddress(&p, g_wz2);  wz2  = (__half*)p;
    cudaGetSymbolAddress(&p, g_wz3);  wz3  = (__half*)p;
    cudaGetSymbolAddress(&p, g_wx0);  wx0  = (__half*)p;
    cudaGetSymbolAddress(&p, g_wx1);  wx1  = (__half*)p;
    cudaGetSymbolAddress(&p, g_wx2);  wx2  = (__half*)p;

    const int nX = BATCH * DIN;
    sub1_half_kernel<<<(nX + 255) / 256, 256>>>(state, xm1, nX);

    const int nW = 4 * HID * DIN + 3 * HID * HID;   // 917504
    prep_weights<<<(nW + 255) / 256, 256>>>(Wz0, Wx0, Wx1, Wx2, Wz1, Wz2, Wz3,
                                            wz0, wx0, wx1, wx2, wz1, wz2, wz3);

    dim3 blk(NTHREADS);
    dim3 gH(HID / BN, BATCH / BM);   // (4, 512)
    dim3 gF(1, BATCH / BM);          // (1, 512)

    // Forward (BT=true: B = W^T, W is [N,K] row-major)
    gemm_h<true, MODE_FWD><<<gH, blk, SMEM_BYTES>>>(xm1, wz0, DIN,
        nullptr, nullptr, 0, nullptr, nullptr, 0, nullptr, nullptr, 0,
        HID, bz0, nullptr, nullptr, s1, a1, nullptr);
    gemm_h<true, MODE_FWD><<<gH, blk, SMEM_BYTES>>>(a1, wz1, HID,
        xm1, wx0, DIN, nullptr, nullptr, 0, nullptr, nullptr, 0,
        HID, bx0, nullptr, nullptr, s2, a2, nullptr);
    gemm_h<true, MODE_FWD><<<gH, blk, SMEM_BYTES>>>(a2, wz2, HID,
        xm1, wx1, DIN, nullptr, nullptr, 0, nullptr, nullptr, 0,
        HID, bx1, nullptr, nullptr, s3, a3, nullptr);
    gemm_h<true, MODE_L4><<<gH, blk, SMEM_BYTES>>>(a3, wz3, HID,
        xm1, wx2, DIN, nullptr, nullptr, 0, nullptr, nullptr, 0,
        HID, bx2, WzL, nullptr, d4, nullptr, nullptr);

    // Backward: d_k = s_k * (d_{k+1} @ Wz_{k+1}); Wz [K,N] row-major -> BT=false
    gemm_h<false, MODE_BWD><<<gH, blk, SMEM_BYTES>>>(d4, wz3, HID,
        nullptr, nullptr, 0, nullptr, nullptr, 0, nullptr, nullptr, 0,
        HID, nullptr, nullptr, s3, d3, nullptr, nullptr);
    gemm_h<false, MODE_BWD><<<gH, blk, SMEM_BYTES>>>(d3, wz2, HID,
        nullptr, nullptr, 0, nullptr, nullptr, 0, nullptr, nullptr, 0,
        HID, nullptr, nullptr, s2, d2, nullptr, nullptr);
    gemm_h<false, MODE_BWD><<<gH, blk, SMEM_BYTES>>>(d2, wz1, HID,
        nullptr, nullptr, 0, nullptr, nullptr, 0, nullptr, nullptr, 0,
        HID, nullptr, nullptr, s1, d1, nullptr, nullptr);

    // Final: action = WxL + d1@Wz0 + d2@Wx0 + d3@Wx1 + d4@Wx2 (all [HID,DIN] = [K,N])
    gemm_h<false, MODE_FIN><<<gF, blk, SMEM_BYTES>>>(d1, wz0, HID,
        d2, wx0, HID, d3, wx1, HID, d4, wx2, HID,
        DIN, nullptr, WxL, nullptr, nullptr, nullptr, out);
}